// round 16
// baseline (speedup 1.0000x reference)
#include <cuda_runtime.h>
#include <math.h>

#define NB 64
#define NW 64
#define NS 1024
#define NCH (NB*NW)

// ---------------- scratch (static device globals; no allocation) ----------------
__device__ float g_V  [NCH*NS];     // current activation (B, W, S)
__device__ float g_PW [NCH*NS];     // pointwise-conv result
__device__ float g_HI [NCH*1078];   // high-pass coeffs levels 1..7 per channel
__device__ float g_LO8[NCH*14];     // coarsest lo (raw)
__device__ float g_HI8[NCH*14];     // coarsest hi (raw)
__device__ float g_MLO[NCH*14];     // coarsest lo (channel-mixed)
__device__ float g_MHI[NCH*14];     // coarsest hi (channel-mixed)

// ---------------- wavelet filter constants (FFMA-imm friendly literals) --------
#define RL0  0.11154074335008017f
#define RL1  0.4946238903983854f
#define RL2  0.7511339080215775f
#define RL3  0.3152503517092432f
#define RL4  (-0.22626469396516913f)
#define RL5  (-0.12976686756709563f)
#define RL6  0.09750160558707936f
#define RL7  0.02752286553001629f
#define RL8  (-0.031582039318031156f)
#define RL9  0.0005538422009938016f
#define RL10 0.004777257511010651f
#define RL11 (-0.00107730108499558f)
// RH[j] = (-1)^j * RL[11-j]
#define RH0  (-0.00107730108499558f)
#define RH1  (-0.004777257511010651f)
#define RH2  0.0005538422009938016f
#define RH3  0.031582039318031156f
#define RH4  0.02752286553001629f
#define RH5  (-0.09750160558707936f)
#define RH6  (-0.12976686756709563f)
#define RH7  0.22626469396516913f
#define RH8  0.3152503517092432f
#define RH9  (-0.7511339080215775f)
#define RH10 0.4946238903983854f
#define RH11 (-0.11154074335008017f)

__device__ __forceinline__ float geluf(float x) {
    return 0.5f * x * (1.0f + erff(x * 0.7071067811865476f));
}

// ---------------- analysis inner body (one output index n) --------------------
__device__ __forceinline__ void afb_body(const float* __restrict__ cur, int N,
                                         int n, float& lo, float& hi) {
    const int base = 2 * n - 10;
    if (base >= 0 && base + 11 < N) {
        const float* xp = cur + base;
        float x0=xp[0],x1=xp[1],x2=xp[2],x3=xp[3],x4=xp[4],x5=xp[5];
        float x6=xp[6],x7=xp[7],x8=xp[8],x9=xp[9],x10=xp[10],x11=xp[11];
        lo = x0*RL0+x1*RL1+x2*RL2+x3*RL3+x4*RL4+x5*RL5
           + x6*RL6+x7*RL7+x8*RL8+x9*RL9+x10*RL10+x11*RL11;
        hi = x0*RH0+x1*RH1+x2*RH2+x3*RH3+x4*RH4+x5*RH5
           + x6*RH6+x7*RH7+x8*RH8+x9*RH9+x10*RH10+x11*RH11;
    } else {
        const float RLa[12]={RL0,RL1,RL2,RL3,RL4,RL5,RL6,RL7,RL8,RL9,RL10,RL11};
        const float RHa[12]={RH0,RH1,RH2,RH3,RH4,RH5,RH6,RH7,RH8,RH9,RH10,RH11};
        lo = 0.f; hi = 0.f;
#pragma unroll
        for (int k = 0; k < 12; k++) {
            int i = base + k;
            i = (i < 0) ? (-1 - i) : i;          // symmetric left reflect
            i = (i >= N) ? (2 * N - 1 - i) : i;  // symmetric right reflect
            float xv = cur[i];
            lo += RLa[k] * xv;
            hi += RHa[k] * xv;
        }
    }
}

// ---------------- warp-level 8-level DWT cascade (A: len 1024, B: scratch) ----
// 2 outputs per lane per iteration: ILP x2, loop ALU halved.
__device__ __forceinline__ void analysis_warp(float* A, float* B, int ch, int lane) {
    float* cur = A; float* nxt = B;
    int N = NS;
    const int offs[7] = {0, 517, 781, 918, 992, 1034, 1060};
#pragma unroll
    for (int l = 0; l < 8; l++) {
        const int out = (N + 11) >> 1;
        float* __restrict__ hidst = (l < 7) ? (g_HI + (size_t)ch * 1078 + offs[l]) : 0;
        int n = lane;
        for (; n + 32 < out; n += 64) {
            float lo0, hi0, lo1, hi1;
            afb_body(cur, N, n,      lo0, hi0);
            afb_body(cur, N, n + 32, lo1, hi1);
            if (l < 7) {
                hidst[n] = hi0; hidst[n + 32] = hi1;
                nxt[n] = lo0;   nxt[n + 32] = lo1;
            } else {
                g_LO8[ch * 14 + n] = lo0; g_HI8[ch * 14 + n] = hi0;
                g_LO8[ch * 14 + n + 32] = lo1; g_HI8[ch * 14 + n + 32] = hi1;
            }
        }
        if (n < out) {
            float lo0, hi0;
            afb_body(cur, N, n, lo0, hi0);
            if (l < 7) { hidst[n] = hi0; nxt[n] = lo0; }
            else       { g_LO8[ch * 14 + n] = lo0; g_HI8[ch * 14 + n] = hi0; }
        }
        __syncwarp();
        float* t = cur; cur = nxt; nxt = t;
        N = out;
    }
}

// ---------------- fc0 + analysis(level 0), warp-per-channel -------------------
__global__ void __launch_bounds__(128) k_fc0an(const float* __restrict__ x,
                                               const float* __restrict__ w0,
                                               const float* __restrict__ b0) {
    const int w = threadIdx.x >> 5, lane = threadIdx.x & 31;
    const int ch = blockIdx.x * 4 + w, b = ch >> 6, c = ch & 63;
    __shared__ __align__(16) float sm[4][1552];   // per warp: A[1024] + B[528]
    float* A = sm[w];
    float* B = sm[w] + 1024;
    const float wa = w0[c], wb = w0[64 + c], bc = b0[c];
    const float4* xb4 = (const float4*)(x + (size_t)b * NS);
    float4* vp4 = (float4*)(g_V + (size_t)ch * NS);
    float4* A4 = (float4*)A;
    for (int q = lane; q < NS / 4; q += 32) {
        float4 xv = xb4[q];
        float s0 = (float)(4 * q);
        float4 r;
        r.x = xv.x * wa + (s0        ) * (1.0f / 1023.0f) * wb + bc;
        r.y = xv.y * wa + (s0 + 1.0f) * (1.0f / 1023.0f) * wb + bc;
        r.z = xv.z * wa + (s0 + 2.0f) * (1.0f / 1023.0f) * wb + bc;
        r.w = xv.w * wa + (s0 + 3.0f) * (1.0f / 1023.0f) * wb + bc;
        A4[q] = r;
        vp4[q] = r;
    }
    __syncwarp();
    analysis_warp(A, B, ch, lane);
}

// ---------------- coarse mix: 28 tiny GEMMs, out[b,o,x] = Σ_i raw[b,i,x]w[i,o,x]
__global__ void __launch_bounds__(256) k_mix(const float* __restrict__ w1,
                                             const float* __restrict__ w2) {
    const int x = blockIdx.x;
    const int which = blockIdx.y;
    const float* __restrict__ raw = which ? g_HI8 : g_LO8;
    const float* __restrict__ wm  = which ? w2 : w1;
    float* __restrict__ dst = which ? g_MHI : g_MLO;
    __shared__ float sA[64][65];  // [b][i]
    __shared__ float sW[64][65];  // [i][o]
    for (int idx = threadIdx.x; idx < 4096; idx += 256) {
        int r = idx >> 6, cc = idx & 63;
        sA[r][cc] = raw[(r * 64 + cc) * 14 + x];   // r=b, cc=i
        sW[r][cc] = wm [(r * 64 + cc) * 14 + x];   // r=i, cc=o
    }
    __syncthreads();
    const int o0 = (threadIdx.x & 15) * 4;
    const int b0 = (threadIdx.x >> 4) * 4;
    float acc[4][4] = {};
    for (int i = 0; i < 64; i++) {
        float a0 = sA[b0 + 0][i], a1 = sA[b0 + 1][i];
        float a2 = sA[b0 + 2][i], a3 = sA[b0 + 3][i];
        float w0v = sW[i][o0 + 0], w1v = sW[i][o0 + 1];
        float w2v = sW[i][o0 + 2], w3v = sW[i][o0 + 3];
        acc[0][0] += a0*w0v; acc[0][1] += a0*w1v; acc[0][2] += a0*w2v; acc[0][3] += a0*w3v;
        acc[1][0] += a1*w0v; acc[1][1] += a1*w1v; acc[1][2] += a1*w2v; acc[1][3] += a1*w3v;
        acc[2][0] += a2*w0v; acc[2][1] += a2*w1v; acc[2][2] += a2*w2v; acc[2][3] += a2*w3v;
        acc[3][0] += a3*w0v; acc[3][1] += a3*w1v; acc[3][2] += a3*w2v; acc[3][3] += a3*w3v;
    }
#pragma unroll
    for (int j = 0; j < 4; j++)
#pragma unroll
        for (int k = 0; k < 4; k++)
            dst[((b0 + j) * 64 + o0 + k) * 14 + x] = acc[j][k];
}

// ---------------- pointwise conv: outer-product tiling, 4 blocks/SM forced ----
__global__ void __launch_bounds__(256, 4) k_pointwise(const float* __restrict__ cw,
                                                      const float* __restrict__ cb) {
    const int b = blockIdx.y;
    const int s0 = blockIdx.x * 128;
    __shared__ __align__(16) float sV[64 * 128];   // [c][s] 32 KB
    __shared__ __align__(16) float sW[64 * 64];    // [o][c] 16 KB
    for (int i = threadIdx.x; i < 4096; i += 256) sW[i] = cw[i];
    {
        const float4* gv4 = (const float4*)g_V;
        float4* sv4 = (float4*)sV;
        for (int i = threadIdx.x; i < 2048; i += 256) {
            int c = i >> 5, j = i & 31;
            sv4[c * 32 + j] = gv4[(size_t)(b * 64 + c) * 256 + (s0 >> 2) + j];
        }
    }
    __syncthreads();
    const int lane = threadIdx.x & 31, og = threadIdx.x >> 5;
    float4 acc[8] = {};
    const float* wbase = sW + og * 8 * 64;
#pragma unroll 4
    for (int c = 0; c < 64; c += 2) {
        float4 v0 = ((const float4*)(sV + c * 128))[lane];
        float4 v1 = ((const float4*)(sV + (c + 1) * 128))[lane];
#pragma unroll
        for (int k = 0; k < 8; k++) {
            float2 w = *(const float2*)(wbase + k * 64 + c);
            acc[k].x += v0.x * w.x + v1.x * w.y;
            acc[k].y += v0.y * w.x + v1.y * w.y;
            acc[k].z += v0.z * w.x + v1.z * w.y;
            acc[k].w += v0.w * w.x + v1.w * w.y;
        }
    }
#pragma unroll
    for (int k = 0; k < 8; k++) {
        const int o = og * 8 + k;
        const float bias = __ldg(&cb[o]);
        float4 r = acc[k];
        r.x += bias; r.y += bias; r.z += bias; r.w += bias;
        ((float4*)(g_PW + (size_t)(b * 64 + o) * NS + s0))[lane] = r;
    }
}

// ---------------- synthesis inner body (one pair index q) ---------------------
__device__ __forceinline__ void sfb_body(const float* __restrict__ lo,
                                         const float* __restrict__ hi,
                                         int q, float& aE, float& aO) {
    int u = q + 5;
    float l = lo[u], h = hi[u];
    aE  = l*RL0  + h*RH0;
    aO  = l*RL1  + h*RH1;
    u--; l = lo[u]; h = hi[u];
    aE += l*RL2  + h*RH2;  aO += l*RL3  + h*RH3;
    u--; l = lo[u]; h = hi[u];
    aE += l*RL4  + h*RH4;  aO += l*RL5  + h*RH5;
    u--; l = lo[u]; h = hi[u];
    aE += l*RL6  + h*RH6;  aO += l*RL7  + h*RH7;
    u--; l = lo[u]; h = hi[u];
    aE += l*RL8  + h*RH8;  aO += l*RL9  + h*RH9;
    u--; l = lo[u]; h = hi[u];
    aE += l*RL10 + h*RH10; aO += l*RL11 + h*RH11;
}

// ---------------- one synthesis level, warp-stride, 2 q per lane --------------
__device__ __forceinline__ void sfb_w(const float* __restrict__ lo,
                                      const float* __restrict__ hi,
                                      float* __restrict__ outb, int N, int lane) {
    const int half = N - 5;  // outLen/2 = (2N-10)/2
    int q = lane;
    for (; q + 32 < half; q += 64) {
        float aE0, aO0, aE1, aO1;
        sfb_body(lo, hi, q,      aE0, aO0);
        sfb_body(lo, hi, q + 32, aE1, aO1);
        ((float2*)outb)[q]      = make_float2(aE0, aO0);
        ((float2*)outb)[q + 32] = make_float2(aE1, aO1);
    }
    if (q < half) {
        float aE0, aO0;
        sfb_body(lo, hi, q, aE0, aO0);
        ((float2*)outb)[q] = make_float2(aE0, aO0);
    }
}

// ---------------- fused synth(l) + gelu + analysis(l+1), warp-per-channel -----
__global__ void __launch_bounds__(128) k_synthan() {
    const int w = threadIdx.x >> 5, lane = threadIdx.x & 31;
    const int ch = blockIdx.x * 4 + w;
    __shared__ __align__(16) float sm[4][1576]; // per warp: X[520] Y[1024] lo[14] hi[14]
    float* X   = sm[w];
    float* Y   = sm[w] + 520;
    float* sLo = sm[w] + 1544;
    float* sHi = sm[w] + 1558;

    if (lane < 14)      sLo[lane]      = g_MLO[ch * 14 + lane];
    else if (lane < 28) sHi[lane - 14] = g_MHI[ch * 14 + lane - 14];
    __syncwarp();

    // synth cascade: 14 ->18 ->26 ->42 ->74 ->138(137) ->264 ->518(517) ->1024
    sfb_w(sLo, sHi, X, 14, lane);
    __syncwarp();
    const float* hibase = g_HI + (size_t)ch * 1078;
    const int hN  [7] = {18, 26, 42, 74, 137, 264, 517};
    const int hOff[7] = {1060, 1034, 992, 918, 781, 517, 0};
    const float* cur = X;
#pragma unroll
    for (int j = 0; j < 7; j++) {
        float* outb = (j & 1) ? X : Y;     // Y,X,Y,X,Y,X,Y
        sfb_w(cur, hibase + hOff[j], outb, hN[j], lane);
        __syncwarp();
        cur = outb;
    }

    // epilogue: V_new = gelu(Y + PW); write to g_V and back into Y in place
    {
        float4* Y4 = (float4*)Y;
        const float4* pw4 = (const float4*)(g_PW + (size_t)ch * NS);
        float4* vout4 = (float4*)(g_V + (size_t)ch * NS);
#pragma unroll 2
        for (int q = lane; q < NS / 4; q += 32) {
            float4 y = Y4[q], p = pw4[q], r;
            r.x = geluf(y.x + p.x); r.y = geluf(y.y + p.y);
            r.z = geluf(y.z + p.z); r.w = geluf(y.w + p.w);
            Y4[q] = r;
            vout4[q] = r;
        }
    }
    __syncwarp();

    // analysis for next layer directly from smem (saves the 16 MB g_V re-read)
    analysis_warp(Y, X, ch, lane);
}

// ---------------- final-layer synthesis (no gelu, no analysis), block/channel -
__device__ __forceinline__ void sfb_pair(const float* __restrict__ lo,
                                         const float* __restrict__ hi,
                                         float* __restrict__ outb, int N) {
    const int half = N - 5;
    for (int q = threadIdx.x; q < half; q += 256) {
        float aE, aO;
        sfb_body(lo, hi, q, aE, aO);
        ((float2*)outb)[q] = make_float2(aE, aO);
    }
}

__global__ void __launch_bounds__(256) k_synth_last() {
    const int ch = blockIdx.x;
    __shared__ __align__(16) float sA[520];
    __shared__ __align__(16) float sB[1024];
    __shared__ float sLo[14], sHi[14];
    if (threadIdx.x < 14)      sLo[threadIdx.x]      = g_MLO[ch * 14 + threadIdx.x];
    else if (threadIdx.x < 28) sHi[threadIdx.x - 14] = g_MHI[ch * 14 + threadIdx.x - 14];
    __syncthreads();
    sfb_pair(sLo, sHi, sA, 14);
    __syncthreads();
    const float* hibase = g_HI + (size_t)ch * 1078;
    const int hN  [7] = {18, 26, 42, 74, 137, 264, 517};
    const int hOff[7] = {1060, 1034, 992, 918, 781, 517, 0};
    const float* cur = sA;
#pragma unroll
    for (int j = 0; j < 7; j++) {
        float* outb = (j & 1) ? sA : sB;
        sfb_pair(cur, hibase + hOff[j], outb, hN[j]);
        __syncthreads();
        cur = outb;
    }
    const float4* pw4 = (const float4*)(g_PW + (size_t)ch * NS);
    float4* vout4 = (float4*)(g_V + (size_t)ch * NS);
    const float4* Y4 = (const float4*)sB;
    for (int q = threadIdx.x; q < NS / 4; q += 256) {
        float4 y = Y4[q], p = pw4[q], r;
        r.x = y.x + p.x; r.y = y.y + p.y;
        r.z = y.z + p.z; r.w = y.w + p.w;
        vout4[q] = r;
    }
}

// ---------------- head: h-dim split across 2 thread-halves, smem reduce -------
__global__ void __launch_bounds__(256) k_fc(const float* __restrict__ w1,
                                            const float* __restrict__ b1,
                                            const float* __restrict__ w2,
                                            const float* __restrict__ b2,
                                            float* __restrict__ out, int add) {
    const int b = blockIdx.y, s0 = blockIdx.x * 128, t = threadIdx.x;
    const int sl = t & 127, hh = t >> 7;        // hh = which h-half
    __shared__ __align__(16) float sW1[128 * 68];   // [h][c] padded
    __shared__ float sB1[128], sW2[128], sRed[128];
    for (int i = t; i < 8192; i += 256) {
        int c = i >> 7, h = i & 127;
        sW1[h * 68 + c] = w1[i];      // w1 is [c][h] row-major
    }
    if (t < 128) { sB1[t] = b1[t]; sW2[t] = w2[t]; }
    float4 vr4[16];
    {
        float* vf = (float*)vr4;
        const float* vbase = g_V + (size_t)b * NW * NS + s0 + sl;
#pragma unroll
        for (int c = 0; c < 64; c++) vf[c] = vbase[(size_t)c * NS];
    }
    __syncthreads();
    float res = 0.f;
    const int h0 = hh * 64;
#pragma unroll 2
    for (int h = h0; h < h0 + 64; h++) {
        const float4* wr = (const float4*)(sW1 + h * 68);
        float a0 = 0, a1 = 0, a2 = 0, a3 = 0;
#pragma unroll
        for (int c4 = 0; c4 < 16; c4++) {
            float4 wv = wr[c4]; float4 v = vr4[c4];
            a0 += v.x * wv.x; a1 += v.y * wv.y; a2 += v.z * wv.z; a3 += v.w * wv.w;
        }
        float hv = (a0 + a2) + (a1 + a3) + sB1[h];
        res += geluf(hv) * sW2[h];
    }
    if (hh) sRed[sl] = res;
    __syncthreads();
    if (!hh) {
        res += sRed[sl] + b2[0];
        int idx = b * NS + s0 + sl;
        if (add) out[idx] += res; else out[idx] = res;
    }
}

// ---------------- launch ------------------------------------------------------
extern "C" void kernel_launch(void* const* d_in, const int* in_sizes, int n_in,
                              void* d_out, int out_size) {
    (void)in_sizes; (void)n_in; (void)out_size;
    const float* x = (const float*)d_in[0];
    float* out = (float*)d_out;
    for (int br = 0; br < 2; br++) {
        const int base = 1 + br * 10;
        const float* fc0_w = (const float*)d_in[base + 0];
        const float* fc0_b = (const float*)d_in[base + 1];
        const float* ww1   = (const float*)d_in[base + 2];
        const float* ww2   = (const float*)d_in[base + 3];
        const float* cw    = (const float*)d_in[base + 4];
        const float* cb    = (const float*)d_in[base + 5];
        const float* f1w   = (const float*)d_in[base + 6];
        const float* f1b   = (const float*)d_in[base + 7];
        const float* f2w   = (const float*)d_in[base + 8];
        const float* f2b   = (const float*)d_in[base + 9];

        k_fc0an<<<NCH / 4, 128>>>(x, fc0_w, fc0_b);      // fc0 + analysis(0)
        for (int l = 0; l < 4; l++) {
            k_mix<<<dim3(14, 2), 256>>>(ww1 + l * 57344, ww2 + l * 57344);
            k_pointwise<<<dim3(8, 64), 256>>>(cw + l * 4096, cb + l * 64);
            if (l < 3) k_synthan<<<NCH / 4, 128>>>();    // synth+gelu+V+analysis(l+1)
            else       k_synth_last<<<NCH, 256>>>();
        }
        k_fc<<<dim3(8, 64), 256>>>(f1w, f1b, f2w, f2b, out, br);
    }
}

// round 17
// speedup vs baseline: 1.5970x; 1.5970x over previous
#include <cuda_runtime.h>
#include <math.h>

#define NB 64
#define NW 64
#define NS 1024
#define NCH (NB*NW)

// ---------------- scratch (static device globals; no allocation) ----------------
__device__ float g_V  [NCH*NS];     // current activation (B, W, S)
__device__ float g_PW [NCH*NS];     // pointwise-conv result
__device__ float g_HI [NCH*1078];   // high-pass coeffs levels 1..7 per channel
__device__ float g_LO8[NCH*14];     // coarsest lo (raw)
__device__ float g_HI8[NCH*14];     // coarsest hi (raw)
__device__ float g_MLO[NCH*14];     // coarsest lo (channel-mixed)
__device__ float g_MHI[NCH*14];     // coarsest hi (channel-mixed)

// ---------------- wavelet filter constants (FFMA-imm friendly literals) --------
#define RL0  0.11154074335008017f
#define RL1  0.4946238903983854f
#define RL2  0.7511339080215775f
#define RL3  0.3152503517092432f
#define RL4  (-0.22626469396516913f)
#define RL5  (-0.12976686756709563f)
#define RL6  0.09750160558707936f
#define RL7  0.02752286553001629f
#define RL8  (-0.031582039318031156f)
#define RL9  0.0005538422009938016f
#define RL10 0.004777257511010651f
#define RL11 (-0.00107730108499558f)
// RH[j] = (-1)^j * RL[11-j]
#define RH0  (-0.00107730108499558f)
#define RH1  (-0.004777257511010651f)
#define RH2  0.0005538422009938016f
#define RH3  0.031582039318031156f
#define RH4  0.02752286553001629f
#define RH5  (-0.09750160558707936f)
#define RH6  (-0.12976686756709563f)
#define RH7  0.22626469396516913f
#define RH8  0.3152503517092432f
#define RH9  (-0.7511339080215775f)
#define RH10 0.4946238903983854f
#define RH11 (-0.11154074335008017f)

__device__ __forceinline__ float geluf(float x) {
    return 0.5f * x * (1.0f + erff(x * 0.7071067811865476f));
}

// ---------------- warp-level 8-level DWT cascade (A: len 1024, B: scratch) ----
__device__ __forceinline__ void analysis_warp(float* A, float* B, int ch, int lane) {
    float* cur = A; float* nxt = B;
    int N = NS;
    const int offs[7] = {0, 517, 781, 918, 992, 1034, 1060};
#pragma unroll
    for (int l = 0; l < 8; l++) {
        const int out = (N + 11) >> 1;
        for (int n = lane; n < out; n += 32) {
            const int base = 2 * n - 10;
            float lo, hi;
            if (base >= 0 && base + 11 < N) {
                const float* xp = cur + base;
                float x0=xp[0],x1=xp[1],x2=xp[2],x3=xp[3],x4=xp[4],x5=xp[5];
                float x6=xp[6],x7=xp[7],x8=xp[8],x9=xp[9],x10=xp[10],x11=xp[11];
                lo = x0*RL0+x1*RL1+x2*RL2+x3*RL3+x4*RL4+x5*RL5
                   + x6*RL6+x7*RL7+x8*RL8+x9*RL9+x10*RL10+x11*RL11;
                hi = x0*RH0+x1*RH1+x2*RH2+x3*RH3+x4*RH4+x5*RH5
                   + x6*RH6+x7*RH7+x8*RH8+x9*RH9+x10*RH10+x11*RH11;
            } else {
                const float RLa[12]={RL0,RL1,RL2,RL3,RL4,RL5,RL6,RL7,RL8,RL9,RL10,RL11};
                const float RHa[12]={RH0,RH1,RH2,RH3,RH4,RH5,RH6,RH7,RH8,RH9,RH10,RH11};
                lo = 0.f; hi = 0.f;
#pragma unroll
                for (int k = 0; k < 12; k++) {
                    int i = base + k;
                    i = (i < 0) ? (-1 - i) : i;          // symmetric left reflect
                    i = (i >= N) ? (2 * N - 1 - i) : i;  // symmetric right reflect
                    float xv = cur[i];
                    lo += RLa[k] * xv;
                    hi += RHa[k] * xv;
                }
            }
            if (l < 7) {
                g_HI[(size_t)ch * 1078 + offs[l] + n] = hi;
                nxt[n] = lo;
            } else {
                g_LO8[ch * 14 + n] = lo;
                g_HI8[ch * 14 + n] = hi;
            }
        }
        __syncwarp();
        float* t = cur; cur = nxt; nxt = t;
        N = out;
    }
}

// ---------------- fc0 + analysis(level 0), warp-per-channel -------------------
__global__ void __launch_bounds__(128) k_fc0an(const float* __restrict__ x,
                                               const float* __restrict__ w0,
                                               const float* __restrict__ b0) {
    const int w = threadIdx.x >> 5, lane = threadIdx.x & 31;
    const int ch = blockIdx.x * 4 + w, b = ch >> 6, c = ch & 63;
    __shared__ __align__(16) float sm[4][1552];   // per warp: A[1024] + B[528]
    float* A = sm[w];
    float* B = sm[w] + 1024;
    const float wa = w0[c], wb = w0[64 + c], bc = b0[c];
    const float4* xb4 = (const float4*)(x + (size_t)b * NS);
    float4* vp4 = (float4*)(g_V + (size_t)ch * NS);
    float4* A4 = (float4*)A;
    for (int q = lane; q < NS / 4; q += 32) {
        float4 xv = xb4[q];
        float s0 = (float)(4 * q);
        float4 r;
        r.x = xv.x * wa + (s0        ) * (1.0f / 1023.0f) * wb + bc;
        r.y = xv.y * wa + (s0 + 1.0f) * (1.0f / 1023.0f) * wb + bc;
        r.z = xv.z * wa + (s0 + 2.0f) * (1.0f / 1023.0f) * wb + bc;
        r.w = xv.w * wa + (s0 + 3.0f) * (1.0f / 1023.0f) * wb + bc;
        A4[q] = r;
        vp4[q] = r;
    }
    __syncwarp();
    analysis_warp(A, B, ch, lane);
}

// ---------------- pointwise conv + fused coarse mix ---------------------------
// Main: outer-product tiling, 8 o-groups x 32 lanes, 4 blocks/SM forced.
// Tail (28 blocks: blockIdx.x==0, blockIdx.y<28): one tiny mix GEMM each,
// out[b,o,x] = sum_i raw[b,i,x]*w[i,o,x], overlaid on the same smem buffer.
__global__ void __launch_bounds__(256, 4) k_pointwise_mix(
        const float* __restrict__ cw, const float* __restrict__ cb,
        const float* __restrict__ w1, const float* __restrict__ w2) {
    const int b = blockIdx.y;
    const int s0 = blockIdx.x * 128;
    __shared__ __align__(16) float smem[12288];    // 48 KB
    float* sV = smem;                              // [c][s] 8192 floats
    float* sW = smem + 8192;                       // [o][c] 4096 floats
    for (int i = threadIdx.x; i < 4096; i += 256) sW[i] = cw[i];
    {
        const float4* gv4 = (const float4*)g_V;
        float4* sv4 = (float4*)sV;
        for (int i = threadIdx.x; i < 2048; i += 256) {
            int c = i >> 5, j = i & 31;
            sv4[c * 32 + j] = gv4[(size_t)(b * 64 + c) * 256 + (s0 >> 2) + j];
        }
    }
    __syncthreads();
    const int lane = threadIdx.x & 31, og = threadIdx.x >> 5;
    {
        float4 acc[8] = {};
        const float* wbase = sW + og * 8 * 64;
#pragma unroll 4
        for (int c = 0; c < 64; c += 2) {
            float4 v0 = ((const float4*)(sV + c * 128))[lane];
            float4 v1 = ((const float4*)(sV + (c + 1) * 128))[lane];
#pragma unroll
            for (int k = 0; k < 8; k++) {
                float2 w = *(const float2*)(wbase + k * 64 + c);
                acc[k].x += v0.x * w.x + v1.x * w.y;
                acc[k].y += v0.y * w.x + v1.y * w.y;
                acc[k].z += v0.z * w.x + v1.z * w.y;
                acc[k].w += v0.w * w.x + v1.w * w.y;
            }
        }
#pragma unroll
        for (int k = 0; k < 8; k++) {
            const int o = og * 8 + k;
            const float bias = __ldg(&cb[o]);
            float4 r = acc[k];
            r.x += bias; r.y += bias; r.z += bias; r.w += bias;
            ((float4*)(g_PW + (size_t)(b * 64 + o) * NS + s0))[lane] = r;
        }
    }

    // ---- fused mix tail: 28 designated blocks -------------------------------
    if (blockIdx.x == 0 && b < 28) {
        const int x = b % 14, which = b / 14;
        const float* __restrict__ raw = which ? g_HI8 : g_LO8;
        const float* __restrict__ wm  = which ? w2 : w1;
        float* __restrict__ dst = which ? g_MHI : g_MLO;
        float* mA = smem;            // [64][65] = 4160 floats
        float* mW = smem + 4160;     // [64][65] = 4160 floats (total 8320 <= 12288)
        __syncthreads();             // main phase fully done with smem
        for (int idx = threadIdx.x; idx < 4096; idx += 256) {
            int r = idx >> 6, cc = idx & 63;
            mA[r * 65 + cc] = raw[(r * 64 + cc) * 14 + x];   // r=batch, cc=i
            mW[r * 65 + cc] = wm [(r * 64 + cc) * 14 + x];   // r=i, cc=o
        }
        __syncthreads();
        const int o0 = (threadIdx.x & 15) * 4;
        const int b0 = (threadIdx.x >> 4) * 4;
        float acc[4][4] = {};
        for (int i = 0; i < 64; i++) {
            float a0 = mA[(b0 + 0) * 65 + i], a1 = mA[(b0 + 1) * 65 + i];
            float a2 = mA[(b0 + 2) * 65 + i], a3 = mA[(b0 + 3) * 65 + i];
            float w0v = mW[i * 65 + o0 + 0], w1v = mW[i * 65 + o0 + 1];
            float w2v = mW[i * 65 + o0 + 2], w3v = mW[i * 65 + o0 + 3];
            acc[0][0] += a0*w0v; acc[0][1] += a0*w1v; acc[0][2] += a0*w2v; acc[0][3] += a0*w3v;
            acc[1][0] += a1*w0v; acc[1][1] += a1*w1v; acc[1][2] += a1*w2v; acc[1][3] += a1*w3v;
            acc[2][0] += a2*w0v; acc[2][1] += a2*w1v; acc[2][2] += a2*w2v; acc[2][3] += a2*w3v;
            acc[3][0] += a3*w0v; acc[3][1] += a3*w1v; acc[3][2] += a3*w2v; acc[3][3] += a3*w3v;
        }
#pragma unroll
        for (int j = 0; j < 4; j++)
#pragma unroll
            for (int k = 0; k < 4; k++)
                dst[((b0 + j) * 64 + o0 + k) * 14 + x] = acc[j][k];
    }
}

// ---------------- one synthesis level, warp-stride ----------------------------
__device__ __forceinline__ void sfb_w(const float* __restrict__ lo,
                                      const float* __restrict__ hi,
                                      float* __restrict__ outb, int N, int lane) {
    const int half = N - 5;  // outLen/2 = (2N-10)/2
    for (int q = lane; q < half; q += 32) {
        int u = q + 5;
        float l = lo[u], h = hi[u];
        float aE = l*RL0  + h*RH0;
        float aO = l*RL1  + h*RH1;
        u--; l = lo[u]; h = hi[u];
        aE += l*RL2  + h*RH2;  aO += l*RL3  + h*RH3;
        u--; l = lo[u]; h = hi[u];
        aE += l*RL4  + h*RH4;  aO += l*RL5  + h*RH5;
        u--; l = lo[u]; h = hi[u];
        aE += l*RL6  + h*RH6;  aO += l*RL7  + h*RH7;
        u--; l = lo[u]; h = hi[u];
        aE += l*RL8  + h*RH8;  aO += l*RL9  + h*RH9;
        u--; l = lo[u]; h = hi[u];
        aE += l*RL10 + h*RH10; aO += l*RL11 + h*RH11;
        ((float2*)outb)[q] = make_float2(aE, aO);
    }
}

// ---------------- fused synth(l) + gelu + analysis(l+1), warp-per-channel -----
__global__ void __launch_bounds__(128) k_synthan() {
    const int w = threadIdx.x >> 5, lane = threadIdx.x & 31;
    const int ch = blockIdx.x * 4 + w;
    __shared__ __align__(16) float sm[4][1576]; // per warp: X[520] Y[1024] lo[14] hi[14]
    float* X   = sm[w];
    float* Y   = sm[w] + 520;
    float* sLo = sm[w] + 1544;
    float* sHi = sm[w] + 1558;

    if (lane < 14)      sLo[lane]      = g_MLO[ch * 14 + lane];
    else if (lane < 28) sHi[lane - 14] = g_MHI[ch * 14 + lane - 14];
    __syncwarp();

    // synth cascade: 14 ->18 ->26 ->42 ->74 ->138(137) ->264 ->518(517) ->1024
    sfb_w(sLo, sHi, X, 14, lane);
    __syncwarp();
    const float* hibase = g_HI + (size_t)ch * 1078;
    const int hN  [7] = {18, 26, 42, 74, 137, 264, 517};
    const int hOff[7] = {1060, 1034, 992, 918, 781, 517, 0};
    const float* cur = X;
#pragma unroll
    for (int j = 0; j < 7; j++) {
        float* outb = (j & 1) ? X : Y;     // Y,X,Y,X,Y,X,Y
        sfb_w(cur, hibase + hOff[j], outb, hN[j], lane);
        __syncwarp();
        cur = outb;
    }

    // epilogue: V_new = gelu(Y + PW); write to g_V and back into Y in place
    {
        float4* Y4 = (float4*)Y;                       // Y offset 2080 B: 16-aligned
        const float4* pw4 = (const float4*)(g_PW + (size_t)ch * NS);
        float4* vout4 = (float4*)(g_V + (size_t)ch * NS);
        for (int q = lane; q < NS / 4; q += 32) {
            float4 y = Y4[q], p = pw4[q], r;
            r.x = geluf(y.x + p.x); r.y = geluf(y.y + p.y);
            r.z = geluf(y.z + p.z); r.w = geluf(y.w + p.w);
            Y4[q] = r;
            vout4[q] = r;
        }
    }
    __syncwarp();

    // analysis for next layer directly from smem (saves the 16 MB g_V re-read)
    analysis_warp(Y, X, ch, lane);
}

// ---------------- final-layer synthesis (no gelu, no analysis), block/channel -
__device__ __forceinline__ void sfb_pair(const float* __restrict__ lo,
                                         const float* __restrict__ hi,
                                         float* __restrict__ outb, int N) {
    const int half = N - 5;
    for (int q = threadIdx.x; q < half; q += 256) {
        int u = q + 5;
        float l = lo[u], h = hi[u];
        float aE = l*RL0  + h*RH0;
        float aO = l*RL1  + h*RH1;
        u--; l = lo[u]; h = hi[u];
        aE += l*RL2  + h*RH2;  aO += l*RL3  + h*RH3;
        u--; l = lo[u]; h = hi[u];
        aE += l*RL4  + h*RH4;  aO += l*RL5  + h*RH5;
        u--; l = lo[u]; h = hi[u];
        aE += l*RL6  + h*RH6;  aO += l*RL7  + h*RH7;
        u--; l = lo[u]; h = hi[u];
        aE += l*RL8  + h*RH8;  aO += l*RL9  + h*RH9;
        u--; l = lo[u]; h = hi[u];
        aE += l*RL10 + h*RH10; aO += l*RL11 + h*RH11;
        ((float2*)outb)[q] = make_float2(aE, aO);
    }
}

__global__ void __launch_bounds__(256) k_synth_last() {
    const int ch = blockIdx.x;
    __shared__ __align__(16) float sA[520];
    __shared__ __align__(16) float sB[1024];
    __shared__ float sLo[14], sHi[14];
    if (threadIdx.x < 14)      sLo[threadIdx.x]      = g_MLO[ch * 14 + threadIdx.x];
    else if (threadIdx.x < 28) sHi[threadIdx.x - 14] = g_MHI[ch * 14 + threadIdx.x - 14];
    __syncthreads();
    sfb_pair(sLo, sHi, sA, 14);
    __syncthreads();
    const float* hibase = g_HI + (size_t)ch * 1078;
    const int hN  [7] = {18, 26, 42, 74, 137, 264, 517};
    const int hOff[7] = {1060, 1034, 992, 918, 781, 517, 0};
    const float* cur = sA;
#pragma unroll
    for (int j = 0; j < 7; j++) {
        float* outb = (j & 1) ? sA : sB;
        sfb_pair(cur, hibase + hOff[j], outb, hN[j]);
        __syncthreads();
        cur = outb;
    }
    const float4* pw4 = (const float4*)(g_PW + (size_t)ch * NS);
    float4* vout4 = (float4*)(g_V + (size_t)ch * NS);
    const float4* Y4 = (const float4*)sB;
    for (int q = threadIdx.x; q < NS / 4; q += 256) {
        float4 y = Y4[q], p = pw4[q], r;
        r.x = y.x + p.x; r.y = y.y + p.y;
        r.z = y.z + p.z; r.w = y.w + p.w;
        vout4[q] = r;
    }
}

// ---------------- head: h-dim split across 2 thread-halves, smem reduce -------
__global__ void __launch_bounds__(256) k_fc(const float* __restrict__ w1,
                                            const float* __restrict__ b1,
                                            const float* __restrict__ w2,
                                            const float* __restrict__ b2,
                                            float* __restrict__ out, int add) {
    const int b = blockIdx.y, s0 = blockIdx.x * 128, t = threadIdx.x;
    const int sl = t & 127, hh = t >> 7;        // hh = which h-half
    __shared__ __align__(16) float sW1[128 * 68];   // [h][c] padded
    __shared__ float sB1[128], sW2[128], sRed[128];
    for (int i = t; i < 8192; i += 256) {
        int c = i >> 7, h = i & 127;
        sW1[h * 68 + c] = w1[i];      // w1 is [c][h] row-major
    }
    if (t < 128) { sB1[t] = b1[t]; sW2[t] = w2[t]; }
    float4 vr4[16];
    {
        float* vf = (float*)vr4;
        const float* vbase = g_V + (size_t)b * NW * NS + s0 + sl;
#pragma unroll
        for (int c = 0; c < 64; c++) vf[c] = vbase[(size_t)c * NS];
    }
    __syncthreads();
    float res = 0.f;
    const int h0 = hh * 64;
#pragma unroll 2
    for (int h = h0; h < h0 + 64; h++) {
        const float4* wr = (const float4*)(sW1 + h * 68);
        float a0 = 0, a1 = 0, a2 = 0, a3 = 0;
#pragma unroll
        for (int c4 = 0; c4 < 16; c4++) {
            float4 wv = wr[c4]; float4 v = vr4[c4];
            a0 += v.x * wv.x; a1 += v.y * wv.y; a2 += v.z * wv.z; a3 += v.w * wv.w;
        }
        float hv = (a0 + a2) + (a1 + a3) + sB1[h];
        res += geluf(hv) * sW2[h];
    }
    if (hh) sRed[sl] = res;
    __syncthreads();
    if (!hh) {
        res += sRed[sl] + b2[0];
        int idx = b * NS + s0 + sl;
        if (add) out[idx] += res; else out[idx] = res;
    }
}

// ---------------- launch ------------------------------------------------------
extern "C" void kernel_launch(void* const* d_in, const int* in_sizes, int n_in,
                              void* d_out, int out_size) {
    (void)in_sizes; (void)n_in; (void)out_size;
    const float* x = (const float*)d_in[0];
    float* out = (float*)d_out;
    for (int br = 0; br < 2; br++) {
        const int base = 1 + br * 10;
        const float* fc0_w = (const float*)d_in[base + 0];
        const float* fc0_b = (const float*)d_in[base + 1];
        const float* ww1   = (const float*)d_in[base + 2];
        const float* ww2   = (const float*)d_in[base + 3];
        const float* cw    = (const float*)d_in[base + 4];
        const float* cb    = (const float*)d_in[base + 5];
        const float* f1w   = (const float*)d_in[base + 6];
        const float* f1b   = (const float*)d_in[base + 7];
        const float* f2w   = (const float*)d_in[base + 8];
        const float* f2b   = (const float*)d_in[base + 9];

        k_fc0an<<<NCH / 4, 128>>>(x, fc0_w, fc0_b);      // fc0 + analysis(0)
        for (int l = 0; l < 4; l++) {
            // pointwise + fused coarse mix (mix feeds the following synthan)
            k_pointwise_mix<<<dim3(8, 64), 256>>>(cw + l * 4096, cb + l * 64,
                                                  ww1 + l * 57344, ww2 + l * 57344);
            if (l < 3) k_synthan<<<NCH / 4, 128>>>();    // synth+gelu+V+analysis(l+1)
            else       k_synth_last<<<NCH, 256>>>();
        }
        k_fc<<<dim3(8, 64), 256>>>(f1w, f1b, f2w, f2b, out, br);
    }
}